// round 9
// baseline (speedup 1.0000x reference)
#include <cuda_runtime.h>
#include <cstdint>

// HistPredictor: splat B*K 2D Gaussians onto 128x128 grids, normalize per batch.
// B=256, K=16, grid 128x128 over [-2,2]^2, MIN_SIGMA=0.001.
//
// R9: R8 math (packed f32x2 exponent recurrence + ex2.approx.f16x2 + packed
// accumulate, lcmax rebase) with 256 threads/CTA x 16 points/thread:
// halves accumulator registers -> ~48 regs, 5 CTAs/SM (40 warps, 2x occ)
// and deeper ILP for the EX2 consumer chain.

#define KMIX 16

__device__ __forceinline__ unsigned long long pack2(float lo, float hi) {
    unsigned long long r;
    asm("mov.b64 %0, {%1, %2};" : "=l"(r) : "f"(lo), "f"(hi));
    return r;
}
__device__ __forceinline__ void unpack2(float& lo, float& hi, unsigned long long p) {
    asm("mov.b64 {%0, %1}, %2;" : "=f"(lo), "=f"(hi) : "l"(p));
}
__device__ __forceinline__ unsigned long long add2(unsigned long long a, unsigned long long b) {
    unsigned long long r;
    asm("add.rn.f32x2 %0, %1, %2;" : "=l"(r) : "l"(a), "l"(b));
    return r;
}

__global__ __launch_bounds__(256, 5) __cluster_dims__(4, 1, 1)
void gmm_hist_kernel(const float* __restrict__ mu,
                     const float* __restrict__ sigma,
                     const float* __restrict__ cov12,
                     const float* __restrict__ pi,
                     float* __restrict__ out)
{
    // log2-domain coefficients: e = a2*du^2 + b2*du*dv + c2*dv^2 + (lc - lcmax)
    __shared__ float s_a[KMIX], s_b[KMIX], s_c[KMIX], s_c2[KMIX];
    __shared__ float s_mu[KMIX], s_mv[KMIX], s_lc[KMIX];
    __shared__ float s_R[KMIX], s_S[KMIX], s_R8[KMIX];
    __shared__ float s_red[8];
    __shared__ float s_part[4];

    const int blk = blockIdx.x;
    const int b = blk >> 2;        // batch
    const int q = blk & 3;         // u-quarter == cluster ctarank
    const int t = threadIdx.x;

    const float H   = 4.0f / 127.0f;
    const float L2E = 1.4426950408889634f;

    if (t < KMIX) {
        const int idx = b * KMIX + t;
        float su = fmaxf(sigma[idx * 2 + 0], 0.001f);
        float sv = fmaxf(sigma[idx * 2 + 1], 0.001f);
        float su2 = su * su;
        float sv2 = sv * sv;
        float c11 = su2 + 1e-6f;
        float c22 = sv2 + 1e-6f;
        float off = cov12[idx];
        float det_full = c11 * c22 - off * off;
        // valid = (det_full > 0) & ~isnan(det_full); NaN>0 is false -> covered.
        float ia, ib, ic, det;
        if (det_full > 0.0f) {
            float rdet = 1.0f / det_full;
            ia = c22 * rdet;
            ib = -off * rdet;
            ic = c11 * rdet;
            det = det_full;
        } else {
            ia = 1.0f / su2;
            ib = 0.0f;
            ic = 1.0f / sv2;
            det = su2 * sv2;
        }
        float a2 = -0.5f * L2E * ia;
        float b2 = -L2E * ib;
        float c2 = -0.5f * L2E * ic;   // strictly < 0
        s_a[t]  = a2;
        s_b[t]  = b2;
        s_c[t]  = c2;
        s_c2[t] = 2.0f * c2;
        float R = c2 * (H * H);        // quadratic-in-j coefficient, < 0
        s_R[t]  = R;
        s_R8[t] = 8.0f * R;
        s_S[t]  = -0.5f / R;
        s_mu[t] = mu[idx * 2 + 0];
        s_mv[t] = mu[idx * 2 + 1];
        float coef = pi[idx] / (6.283185307179586f * sqrtf(det + 1e-6f));
        s_lc[t]   = __log2f(coef);     // -inf for coef==0
    }
    __syncthreads();

    // rebase: exponents shifted by -lcmax (<=0, f16-safe); cancels in normalize
    float lcmax = s_lc[0];
#pragma unroll
    for (int k = 1; k < KMIX; k++) lcmax = fmaxf(lcmax, s_lc[k]);

    // Thread t owns u = q*32 + (t>>3), v in [(t&7)*16, +16)
    const int u  = q * 32 + (t >> 3);
    const int v0 = (t & 7) * 16;
    const float uc    = -2.0f + (float)u  * H;
    const float vbase = -2.0f + (float)v0 * H;

    unsigned long long acc[8];    // packed f32 pairs (j even, j odd)
#pragma unroll
    for (int i = 0; i < 8; i++) acc[i] = 0ull;

#pragma unroll 1
    for (int k = 0; k < KMIX; k++) {
        const float du  = uc    - s_mu[k];
        const float dv0 = vbase - s_mv[k];
        // e(j) = P' + Q*j + R*j^2,  dv = dv0 + j*H,  P' includes lc - lcmax
        const float R = s_R[k];
        const float Q = fmaf(s_c2[k], dv0, s_b[k] * du) * H;
        const float P = fmaf(fmaf(s_b[k], dv0, s_a[k] * du), du,
                             fmaf(s_c[k] * dv0, dv0, s_lc[k] - lcmax));

        // warp-uniform skip: max of concave e' over j in [0,15] vs -16
        float jc = fminf(fmaxf(Q * s_S[k], 0.0f), 15.0f);
        float ev = fmaf(jc, fmaf(R, jc, Q), P);
        if (__ballot_sync(0xffffffffu, ev >= -16.0f) == 0u) continue;

        // packed incremental recurrence over pairs (j=2i, 2i+1):
        //   ep_{i+1} = ep_i + dp_i ;  dp_{i+1} = dp_i + (8R, 8R)
        unsigned long long ep = pack2(P, P + Q + R);
        unsigned long long dp = pack2(2.0f * Q + 4.0f * R, 2.0f * Q + 8.0f * R);
        const unsigned long long stp = pack2(s_R8[k], s_R8[k]);

#pragma unroll
        for (int i = 0; i < 8; i++) {
            float elo, ehi;
            unpack2(elo, ehi, ep);
            uint32_t g2;
            asm("{\n\t"
                ".reg .b32 h2;\n\t"
                "cvt.rn.f16x2.f32 h2, %1, %2;\n\t"    // hi = ehi, lo = elo
                "ex2.approx.f16x2 %0, h2;\n\t"
                "}"
                : "=r"(g2) : "f"(ehi), "f"(elo));
            float g0, g1;
            asm("{\n\t"
                ".reg .b16 lo, hi;\n\t"
                "mov.b32 {lo, hi}, %2;\n\t"
                "cvt.f32.f16 %0, lo;\n\t"
                "cvt.f32.f16 %1, hi;\n\t"
                "}"
                : "=f"(g0), "=f"(g1) : "r"(g2));
            acc[i] = add2(acc[i], pack2(g0, g1));     // packed accumulate
            ep = add2(ep, dp);
            dp = add2(dp, stp);
        }
    }

    // CTA partial sum (this u-quarter, rebased domain)
    float s = 0.0f;
#pragma unroll
    for (int i = 0; i < 8; i++) {
        float lo, hi;
        unpack2(lo, hi, acc[i]);
        s += lo + hi;
    }
#pragma unroll
    for (int o = 16; o > 0; o >>= 1) s += __shfl_xor_sync(0xffffffffu, s, o);
    const int warp = t >> 5;
    const int lane = t & 31;
    if (lane == 0) s_red[warp] = s;
    __syncthreads();

    // Thread 0 scatters this CTA's partial into slot q of all 4 cluster CTAs.
    if (t == 0) {
        float mysum = 0.0f;
#pragma unroll
        for (int w = 0; w < 8; w++) mysum += s_red[w];
        uint32_t laddr;
        asm("{ .reg .u64 tmp; cvta.to.shared.u64 tmp, %1; cvt.u32.u64 %0, tmp; }"
            : "=r"(laddr) : "l"(&s_part[q]));
#pragma unroll
        for (int r = 0; r < 4; r++) {
            uint32_t raddr;
            asm("mapa.shared::cluster.u32 %0, %1, %2;" : "=r"(raddr) : "r"(laddr), "r"(r));
            asm volatile("st.shared::cluster.f32 [%0], %1;" :: "r"(raddr), "f"(mysum)
                         : "memory");
        }
    }
    // Cluster barrier: arrive(release) orders the DSMEM stores; wait(acquire)
    // makes all 4 partials visible in local s_part.
    asm volatile("barrier.cluster.arrive.aligned;" ::: "memory");
    asm volatile("barrier.cluster.wait.aligned;"   ::: "memory");

    const float tot = (s_part[0] + s_part[1]) + (s_part[2] + s_part[3]);
    const float inv = (tot > 0.0f) ? (1.0f / tot) : 1.0f;   // 2^lcmax cancels

    // normalized store (coalesced float4)
    float* op = out + (size_t)b * 16384 + (size_t)u * 128 + v0;
#pragma unroll
    for (int i = 0; i < 8; i += 2) {
        float x0, x1, x2, x3;
        unpack2(x0, x1, acc[i]);
        unpack2(x2, x3, acc[i + 1]);
        *reinterpret_cast<float4*>(op + i * 2) =
            make_float4(x0 * inv, x1 * inv, x2 * inv, x3 * inv);
    }
}

extern "C" void kernel_launch(void* const* d_in, const int* in_sizes, int n_in,
                              void* d_out, int out_size)
{
    const float* mu    = (const float*)d_in[0];
    const float* sigma = (const float*)d_in[1];
    const float* cov12 = (const float*)d_in[2];
    const float* pi    = (const float*)d_in[3];
    float* out = (float*)d_out;
    gmm_hist_kernel<<<1024, 256>>>(mu, sigma, cov12, pi, out);
}

// round 10
// speedup vs baseline: 1.0326x; 1.0326x over previous
#include <cuda_runtime.h>
#include <cstdint>

// HistPredictor: splat B*K 2D Gaussians onto 128x128 grids, normalize per batch.
// B=256, K=16, grid 128x128 over [-2,2]^2, MIN_SIGMA=0.001.
//
// R10: R8 structure (4-CTA cluster, DSMEM norm, packed f32x2 exponent
// recurrence, ex2.approx.f16x2) but the f16->f32 unpack is done with ALU bit
// ops ((bits<<13)&mask viewed as f32, scaled by 2^112 inside a packed FMA)
// instead of cvt.f32.f16 -- removes 8 XU cycles per 2 points from the
// binding pipe. Bit transform is exact for normals AND subnormals.

#define KMIX 16

__device__ __forceinline__ unsigned long long pack2(float lo, float hi) {
    unsigned long long r;
    asm("mov.b64 %0, {%1, %2};" : "=l"(r) : "f"(lo), "f"(hi));
    return r;
}
__device__ __forceinline__ void unpack2(float& lo, float& hi, unsigned long long p) {
    asm("mov.b64 {%0, %1}, %2;" : "=f"(lo), "=f"(hi) : "l"(p));
}
__device__ __forceinline__ unsigned long long add2(unsigned long long a, unsigned long long b) {
    unsigned long long r;
    asm("add.rn.f32x2 %0, %1, %2;" : "=l"(r) : "l"(a), "l"(b));
    return r;
}
__device__ __forceinline__ unsigned long long fma2(unsigned long long a, unsigned long long b,
                                                   unsigned long long c) {
    unsigned long long r;
    asm("fma.rn.f32x2 %0, %1, %2, %3;" : "=l"(r) : "l"(a), "l"(b), "l"(c));
    return r;
}

__global__ __launch_bounds__(128, 8) __cluster_dims__(4, 1, 1)
void gmm_hist_kernel(const float* __restrict__ mu,
                     const float* __restrict__ sigma,
                     const float* __restrict__ cov12,
                     const float* __restrict__ pi,
                     float* __restrict__ out)
{
    // log2-domain coefficients: e = a2*du^2 + b2*du*dv + c2*dv^2 + (lc - lcmax)
    __shared__ float s_a[KMIX], s_b[KMIX], s_c[KMIX], s_c2[KMIX];
    __shared__ float s_mu[KMIX], s_mv[KMIX], s_lc[KMIX];
    __shared__ float s_R[KMIX], s_S[KMIX], s_R8[KMIX];
    __shared__ float s_red[4];
    __shared__ float s_part[4];

    const int blk = blockIdx.x;
    const int b = blk >> 2;        // batch
    const int q = blk & 3;         // u-quarter == cluster ctarank
    const int t = threadIdx.x;

    const float H   = 4.0f / 127.0f;
    const float L2E = 1.4426950408889634f;

    if (t < KMIX) {
        const int idx = b * KMIX + t;
        float su = fmaxf(sigma[idx * 2 + 0], 0.001f);
        float sv = fmaxf(sigma[idx * 2 + 1], 0.001f);
        float su2 = su * su;
        float sv2 = sv * sv;
        float c11 = su2 + 1e-6f;
        float c22 = sv2 + 1e-6f;
        float off = cov12[idx];
        float det_full = c11 * c22 - off * off;
        // valid = (det_full > 0) & ~isnan(det_full); NaN>0 is false -> covered.
        float ia, ib, ic, det;
        if (det_full > 0.0f) {
            float rdet = 1.0f / det_full;
            ia = c22 * rdet;
            ib = -off * rdet;
            ic = c11 * rdet;
            det = det_full;
        } else {
            ia = 1.0f / su2;
            ib = 0.0f;
            ic = 1.0f / sv2;
            det = su2 * sv2;
        }
        float a2 = -0.5f * L2E * ia;
        float b2 = -L2E * ib;
        float c2 = -0.5f * L2E * ic;   // strictly < 0
        s_a[t]  = a2;
        s_b[t]  = b2;
        s_c[t]  = c2;
        s_c2[t] = 2.0f * c2;
        float R = c2 * (H * H);        // quadratic-in-j coefficient, < 0
        s_R[t]  = R;
        s_R8[t] = 8.0f * R;
        s_S[t]  = -0.5f / R;
        s_mu[t] = mu[idx * 2 + 0];
        s_mv[t] = mu[idx * 2 + 1];
        float coef = pi[idx] / (6.283185307179586f * sqrtf(det + 1e-6f));
        s_lc[t]   = __log2f(coef);     // -inf for coef==0
    }
    __syncthreads();

    // rebase: exponents shifted by -lcmax (<=0, f16-safe); cancels in normalize
    float lcmax = s_lc[0];
#pragma unroll
    for (int k = 1; k < KMIX; k++) lcmax = fmaxf(lcmax, s_lc[k]);

    // Thread t owns u = q*32 + (t>>2), v in [(t&3)*32, +32)
    const int u  = q * 32 + (t >> 2);
    const int v0 = (t & 3) * 32;
    const float uc    = -2.0f + (float)u  * H;
    const float vbase = -2.0f + (float)v0 * H;

    // scale pair (2^112, 2^112): converts "f16 bits <<13" f32 views to values
    const float SC = __uint_as_float(0x77800000u);
    const unsigned long long scp = pack2(SC, SC);

    unsigned long long acc[16];   // packed f32 pairs (j even, j odd)
#pragma unroll
    for (int i = 0; i < 16; i++) acc[i] = 0ull;

#pragma unroll 1
    for (int k = 0; k < KMIX; k++) {
        const float du  = uc    - s_mu[k];
        const float dv0 = vbase - s_mv[k];
        // e(j) = P' + Q*j + R*j^2,  dv = dv0 + j*H,  P' includes lc - lcmax
        const float R = s_R[k];
        const float Q = fmaf(s_c2[k], dv0, s_b[k] * du) * H;
        const float P = fmaf(fmaf(s_b[k], dv0, s_a[k] * du), du,
                             fmaf(s_c[k] * dv0, dv0, s_lc[k] - lcmax));

        // warp-uniform skip: max of concave e' over j in [0,31] vs -20
        float jc = fminf(fmaxf(Q * s_S[k], 0.0f), 31.0f);
        float ev = fmaf(jc, fmaf(R, jc, Q), P);
        if (__ballot_sync(0xffffffffu, ev >= -20.0f) == 0u) continue;

        // packed incremental recurrence over pairs (j=2i, 2i+1):
        //   ep_{i+1} = ep_i + dp_i ;  dp_{i+1} = dp_i + (8R, 8R)
        unsigned long long ep = pack2(P, P + Q + R);
        unsigned long long dp = pack2(2.0f * Q + 4.0f * R, 2.0f * Q + 8.0f * R);
        const unsigned long long stp = pack2(s_R8[k], s_R8[k]);

#pragma unroll
        for (int i = 0; i < 16; i++) {
            float elo, ehi;
            unpack2(elo, ehi, ep);
            uint32_t g2;
            asm("{\n\t"
                ".reg .b32 h2;\n\t"
                "cvt.rn.f16x2.f32 h2, %1, %2;\n\t"    // hi = ehi, lo = elo
                "ex2.approx.f16x2 %0, h2;\n\t"
                "}"
                : "=r"(g2) : "f"(ehi), "f"(elo));
            // f16 -> f32 via ALU bit ops (exact, incl. subnormals):
            //   f32_bits = (h16_bits << 13) & 0x0FFFE000 ; value = bits * 2^112
            uint32_t lo_b = (g2 << 13) & 0x0FFFE000u;
            uint32_t hi_b = (g2 >> 3)  & 0x0FFFE000u;
            unsigned long long gp = pack2(__uint_as_float(lo_b), __uint_as_float(hi_b));
            acc[i] = fma2(gp, scp, acc[i]);           // scale + accumulate
            ep = add2(ep, dp);
            dp = add2(dp, stp);
        }
    }

    // CTA partial sum (this u-quarter, rebased domain)
    float s = 0.0f;
#pragma unroll
    for (int i = 0; i < 16; i++) {
        float lo, hi;
        unpack2(lo, hi, acc[i]);
        s += lo + hi;
    }
#pragma unroll
    for (int o = 16; o > 0; o >>= 1) s += __shfl_xor_sync(0xffffffffu, s, o);
    const int warp = t >> 5;
    const int lane = t & 31;
    if (lane == 0) s_red[warp] = s;
    __syncthreads();

    // Thread 0 scatters this CTA's partial into slot q of all 4 cluster CTAs.
    if (t == 0) {
        float mysum = s_red[0] + s_red[1] + s_red[2] + s_red[3];
        uint32_t laddr;
        asm("{ .reg .u64 tmp; cvta.to.shared.u64 tmp, %1; cvt.u32.u64 %0, tmp; }"
            : "=r"(laddr) : "l"(&s_part[q]));
#pragma unroll
        for (int r = 0; r < 4; r++) {
            uint32_t raddr;
            asm("mapa.shared::cluster.u32 %0, %1, %2;" : "=r"(raddr) : "r"(laddr), "r"(r));
            asm volatile("st.shared::cluster.f32 [%0], %1;" :: "r"(raddr), "f"(mysum)
                         : "memory");
        }
    }
    // Cluster barrier: arrive(release) orders the DSMEM stores; wait(acquire)
    // makes all 4 partials visible in local s_part.
    asm volatile("barrier.cluster.arrive.aligned;" ::: "memory");
    asm volatile("barrier.cluster.wait.aligned;"   ::: "memory");

    const float tot = (s_part[0] + s_part[1]) + (s_part[2] + s_part[3]);
    const float inv = (tot > 0.0f) ? (1.0f / tot) : 1.0f;   // 2^lcmax cancels

    // normalized store (coalesced float4)
    float* op = out + (size_t)b * 16384 + (size_t)u * 128 + v0;
#pragma unroll
    for (int i = 0; i < 16; i += 2) {
        float x0, x1, x2, x3;
        unpack2(x0, x1, acc[i]);
        unpack2(x2, x3, acc[i + 1]);
        *reinterpret_cast<float4*>(op + i * 2) =
            make_float4(x0 * inv, x1 * inv, x2 * inv, x3 * inv);
    }
}

extern "C" void kernel_launch(void* const* d_in, const int* in_sizes, int n_in,
                              void* d_out, int out_size)
{
    const float* mu    = (const float*)d_in[0];
    const float* sigma = (const float*)d_in[1];
    const float* cov12 = (const float*)d_in[2];
    const float* pi    = (const float*)d_in[3];
    float* out = (float*)d_out;
    gmm_hist_kernel<<<1024, 128>>>(mu, sigma, cov12, pi, out);
}

// round 11
// speedup vs baseline: 1.0997x; 1.0650x over previous
#include <cuda_runtime.h>
#include <cstdint>

// HistPredictor: splat B*K 2D Gaussians onto 128x128 grids, normalize per batch.
// B=256, K=16, grid 128x128 over [-2,2]^2, MIN_SIGMA=0.001.
//
// R11: 4-CTA cluster per batch + DSMEM norm (as R4/R8). Inner loop replaces
// per-point EX2 with a geometric recurrence: 4 interleaved chains
//   g_c(i+1) = g_c(i) * T_c(i),  T_c(i+1) = T_c(i) * S4   (S4 = 2^(32R) < 1)
// seeded by 8 EX2s per (warp,k) row. Fast path taken only when the row's
// exponent span <= 100 (warp-uniform ballot) -> no overflow/underflow hazard;
// steep rows fall back to scalar EX2 per point. Full f32 precision.

#define KMIX 16

__device__ __forceinline__ float ex2f(float x) {
    float r;
    asm("ex2.approx.f32 %0, %1;" : "=f"(r) : "f"(x));
    return r;
}

__global__ __launch_bounds__(128, 8) __cluster_dims__(4, 1, 1)
void gmm_hist_kernel(const float* __restrict__ mu,
                     const float* __restrict__ sigma,
                     const float* __restrict__ cov12,
                     const float* __restrict__ pi,
                     float* __restrict__ out)
{
    // log2-domain coefficients: e = a2*du^2 + b2*du*dv + c2*dv^2 + (lc - lcmax)
    __shared__ float s_a[KMIX], s_b[KMIX], s_c[KMIX], s_c2[KMIX];
    __shared__ float s_mu[KMIX], s_mv[KMIX], s_lc[KMIX];
    __shared__ float s_R[KMIX], s_S[KMIX], s_S4[KMIX];
    __shared__ float s_red[4];
    __shared__ float s_part[4];

    const int blk = blockIdx.x;
    const int b = blk >> 2;        // batch
    const int q = blk & 3;         // u-quarter == cluster ctarank
    const int t = threadIdx.x;

    const float H   = 4.0f / 127.0f;
    const float L2E = 1.4426950408889634f;

    if (t < KMIX) {
        const int idx = b * KMIX + t;
        float su = fmaxf(sigma[idx * 2 + 0], 0.001f);
        float sv = fmaxf(sigma[idx * 2 + 1], 0.001f);
        float su2 = su * su;
        float sv2 = sv * sv;
        float c11 = su2 + 1e-6f;
        float c22 = sv2 + 1e-6f;
        float off = cov12[idx];
        float det_full = c11 * c22 - off * off;
        // valid = (det_full > 0) & ~isnan(det_full); NaN>0 is false -> covered.
        float ia, ib, ic, det;
        if (det_full > 0.0f) {
            float rdet = 1.0f / det_full;
            ia = c22 * rdet;
            ib = -off * rdet;
            ic = c11 * rdet;
            det = det_full;
        } else {
            ia = 1.0f / su2;
            ib = 0.0f;
            ic = 1.0f / sv2;
            det = su2 * sv2;
        }
        float a2 = -0.5f * L2E * ia;
        float b2 = -L2E * ib;
        float c2 = -0.5f * L2E * ic;   // strictly < 0
        s_a[t]  = a2;
        s_b[t]  = b2;
        s_c[t]  = c2;
        s_c2[t] = 2.0f * c2;
        float R = c2 * (H * H);        // quadratic-in-j coefficient, < 0
        s_R[t]  = R;
        s_S[t]  = -0.5f / R;
        s_S4[t] = ex2f(32.0f * R);     // common 4-step ratio decay, in (0,1]
        s_mu[t] = mu[idx * 2 + 0];
        s_mv[t] = mu[idx * 2 + 1];
        float coef = pi[idx] / (6.283185307179586f * sqrtf(det + 1e-6f));
        s_lc[t]   = __log2f(coef);     // -inf for coef==0
    }
    __syncthreads();

    // rebase by lcmax (cancels in normalization; improves underflow margin)
    float lcmax = s_lc[0];
#pragma unroll
    for (int k = 1; k < KMIX; k++) lcmax = fmaxf(lcmax, s_lc[k]);

    // Thread t owns u = q*32 + (t>>2), v in [(t&3)*32, +32)
    const int u  = q * 32 + (t >> 2);
    const int v0 = (t & 3) * 32;
    const float uc    = -2.0f + (float)u  * H;
    const float vbase = -2.0f + (float)v0 * H;

    float acc[32];
#pragma unroll
    for (int j = 0; j < 32; j++) acc[j] = 0.0f;

#pragma unroll 1
    for (int k = 0; k < KMIX; k++) {
        const float du  = uc    - s_mu[k];
        const float dv0 = vbase - s_mv[k];
        // e(j) = P' + Q*j + R*j^2,  dv = dv0 + j*H,  P' includes lc - lcmax
        const float R = s_R[k];
        const float Q = fmaf(s_c2[k], dv0, s_b[k] * du) * H;
        const float P = fmaf(fmaf(s_b[k], dv0, s_a[k] * du), du,
                             fmaf(s_c[k] * dv0, dv0, s_lc[k] - lcmax));

        // warp-uniform skip: max of concave e over j in [0,31] vs -20
        float jc = fminf(fmaxf(Q * s_S[k], 0.0f), 31.0f);
        float ev = fmaf(jc, fmaf(R, jc, Q), P);
        if (__ballot_sync(0xffffffffu, ev >= -20.0f) == 0u) continue;

        // span test: fast geometric path only if every lane's row is "shallow"
        float e31 = fmaf(31.0f, fmaf(R, 31.0f, Q), P);
        bool lane_steep = (ev >= -20.0f) && ((ev - fminf(P, e31)) > 100.0f);

        if (__any_sync(0xffffffffu, lane_steep)) {
            // -------- slow path (steep/narrow rows): scalar EX2 per point ---
#pragma unroll
            for (int j = 0; j < 32; j++) {
                const float jf = (float)j;
                float e = fmaf(jf, fmaf(R, jf, Q), P);
                acc[j] += ex2f(e);
            }
        } else {
            // -------- fast path: 4 interleaved geometric chains -------------
            // seeds: g_c = 2^e(c), T_c = 2^(e(c+4)-e(c)) = 2^(4Q + R(8c+16))
            const float S4 = s_S4[k];
            float g0 = ex2f(P);
            float g1 = ex2f(P + Q + R);
            float g2 = ex2f(fmaf(2.0f, fmaf(R, 2.0f, Q), P));
            float g3 = ex2f(fmaf(3.0f, fmaf(R, 3.0f, Q), P));
            const float fourQ = 4.0f * Q;
            // clamp ratio exponents so dead lanes (g underflowed to 0) stay 0
            float T0 = ex2f(fminf(fmaf(16.0f, R, fourQ), 120.0f));
            float T1 = ex2f(fminf(fmaf(24.0f, R, fourQ), 120.0f));
            float T2 = ex2f(fminf(fmaf(32.0f, R, fourQ), 120.0f));
            float T3 = ex2f(fminf(fmaf(40.0f, R, fourQ), 120.0f));
#pragma unroll
            for (int i = 0; i < 8; i++) {
                acc[4 * i + 0] += g0;
                acc[4 * i + 1] += g1;
                acc[4 * i + 2] += g2;
                acc[4 * i + 3] += g3;
                g0 *= T0;  g1 *= T1;  g2 *= T2;  g3 *= T3;
                T0 *= S4;  T1 *= S4;  T2 *= S4;  T3 *= S4;
            }
        }
    }

    // CTA partial sum (this u-quarter, rebased domain)
    float s = 0.0f;
#pragma unroll
    for (int j = 0; j < 32; j++) s += acc[j];
#pragma unroll
    for (int o = 16; o > 0; o >>= 1) s += __shfl_xor_sync(0xffffffffu, s, o);
    const int warp = t >> 5;
    const int lane = t & 31;
    if (lane == 0) s_red[warp] = s;
    __syncthreads();

    // Thread 0 scatters this CTA's partial into slot q of all 4 cluster CTAs.
    if (t == 0) {
        float mysum = s_red[0] + s_red[1] + s_red[2] + s_red[3];
        uint32_t laddr;
        asm("{ .reg .u64 tmp; cvta.to.shared.u64 tmp, %1; cvt.u32.u64 %0, tmp; }"
            : "=r"(laddr) : "l"(&s_part[q]));
#pragma unroll
        for (int r = 0; r < 4; r++) {
            uint32_t raddr;
            asm("mapa.shared::cluster.u32 %0, %1, %2;" : "=r"(raddr) : "r"(laddr), "r"(r));
            asm volatile("st.shared::cluster.f32 [%0], %1;" :: "r"(raddr), "f"(mysum)
                         : "memory");
        }
    }
    // Cluster barrier: arrive(release) orders the DSMEM stores; wait(acquire)
    // makes all 4 partials visible in local s_part.
    asm volatile("barrier.cluster.arrive.aligned;" ::: "memory");
    asm volatile("barrier.cluster.wait.aligned;"   ::: "memory");

    const float tot = (s_part[0] + s_part[1]) + (s_part[2] + s_part[3]);
    const float inv = (tot > 0.0f) ? (1.0f / tot) : 1.0f;   // 2^lcmax cancels

    // normalized store (coalesced float4)
    float* op = out + (size_t)b * 16384 + (size_t)u * 128 + v0;
#pragma unroll
    for (int j = 0; j < 32; j += 4) {
        float4 w = make_float4(acc[j] * inv, acc[j + 1] * inv,
                               acc[j + 2] * inv, acc[j + 3] * inv);
        *reinterpret_cast<float4*>(op + j) = w;
    }
}

extern "C" void kernel_launch(void* const* d_in, const int* in_sizes, int n_in,
                              void* d_out, int out_size)
{
    const float* mu    = (const float*)d_in[0];
    const float* sigma = (const float*)d_in[1];
    const float* cov12 = (const float*)d_in[2];
    const float* pi    = (const float*)d_in[3];
    float* out = (float*)d_out;
    gmm_hist_kernel<<<1024, 128>>>(mu, sigma, cov12, pi, out);
}